// round 17
// baseline (speedup 1.0000x reference)
#include <cuda_runtime.h>

typedef unsigned long long ull;

#define NTOT 51840000   // 405*80*80*20

__device__ float g_mask1[6400];
__device__ float g_mask2[6400];

__global__ void mask_prep(const float* __restrict__ a1, const float* __restrict__ a2)
{
    int p = blockIdx.x * blockDim.x + threadIdx.x;
    if (p < 6400) {
        float s1 = 0.f, s2 = 0.f;
        const float* p1 = a1 + p * 20;
        const float* p2 = a2 + p * 20;
        #pragma unroll
        for (int z = 0; z < 20; ++z) { s1 += p1[z]; s2 += p2[z]; }
        g_mask1[p] = fminf(fmaxf(s1, 0.f), 1.f);
        g_mask2[p] = fminf(fmaxf(s2, 0.f), 1.f);
    }
}

__device__ __forceinline__ void unpack2(ull v, float& lo, float& hi) {
    asm("mov.b64 {%0, %1}, %2;" : "=f"(lo), "=f"(hi) : "l"(v));
}
__device__ __forceinline__ void fma2(ull& d, ull a, ull b) {
    asm("fma.rn.f32x2 %0, %1, %2, %0;" : "+l"(d) : "l"(a), "l"(b));
}
__device__ __forceinline__ ull shiftpair(ull a, ull b) {
    ull r;
    asm("{\n\t.reg .b32 alo, ahi, blo, bhi;\n\t"
        "mov.b64 {alo, ahi}, %1;\n\t"
        "mov.b64 {blo, bhi}, %2;\n\t"
        "mov.b64 %0, {ahi, blo};\n\t}"
        : "=l"(r) : "l"(a), "l"(b));
    return r;
}
__device__ __forceinline__ void cp16(unsigned dst, const void* src) {
    asm volatile("cp.async.cg.shared.global [%0], [%1], 16;" :: "r"(dst), "l"(src));
}
__device__ __forceinline__ void cp_commit() {
    asm volatile("cp.async.commit_group;" ::: "memory");
}
template<int N> __device__ __forceinline__ void cp_wait() {
    asm volatile("cp.async.wait_group %0;" :: "n"(N) : "memory");
}

// b-window for one channel at z-pair grain (6 regs): pairs 1+zp, 2+zp, 3+zp
struct BW { ull E0, E1, E2; };

__device__ __forceinline__ void loadB(BW& b, const ull* f2p, int cl, int bq0)
{
    const ull* bp = f2p + cl * 416 + bq0;
    b.E0 = bp[0];
    b.E1 = bp[1];
    b.E2 = bp[2];
}
__device__ __forceinline__ ull loadA(const ull* f1p, int cl, int aq)
{
    return f1p[cl * 240 + aq];
}

// 5 fma2 for one (channel, jl): dk 0..4 on one z-pair
__device__ __forceinline__ void fma5(ull* A, ull a, const BW& b, ull O1, ull O3)
{
    fma2(A[0], a, b.E0);   // dk=0
    fma2(A[1], a, O1  );   // dk=1
    fma2(A[2], a, b.E1);   // dk=2
    fma2(A[3], a, O3  );   // dk=3
    fma2(A[4], a, b.E2);   // dk=4
}

// block: 480 threads, tid = zp + 10*x2c + 160*djg (zp fastest -> coalesced stores)
// grid : (x2b 6, y 80, dig 3); block loops dil 0..2, di = dig*3 + dil
// f1 RESIDENT: f1s [c32][xl24][zp10] pairs = 61440 B (byte-identical to quad layout)
// f2 double-buffered, 4 phases x 8 channels per di:
//   buf [c8][x2 16][26 pairs] = 26624 B each; pairs 0,1 & 12,13 zero guards,
//   pairs 2..11 = z-pairs 0..9 (quad layout from prior rounds, reinterpreted)
// smem = 61440 + 2*26624 = 114688 B -> 2 blocks/SM, 960 thr (68 regs cap)
#define F2B 26624
#define F2BASE 61440          // bytes
#define F2BASEQ 3840          // quads
#define CADV 1024000          // 8 channels * 128000 floats

__global__ void __launch_bounds__(480, 2) corr_kernel(
    const float* __restrict__ f1, const float* __restrict__ f2, float* __restrict__ out)
{
    extern __shared__ float smem[];
    const unsigned sb = (unsigned)__cvta_generic_to_shared(smem);

    const int x2b  = blockIdx.x;
    const int y    = blockIdx.y;
    const int dig  = blockIdx.z;
    const int x2g0 = x2b * 16 - 4;
    const int y2_0 = y + dig * 3 - 4;          // y2 at dil=0
    const int tid  = threadIdx.x;

    const int zp  = tid % 10;                  // z-pair: z = 2*zp, 2*zp+1
    const int x2c = (tid / 10) & 15;
    const int djg = tid / 160;
    const int x2g = x2g0 + x2c;

    const bool anyok = (y2_0 + 2 >= 0) && (y2_0 < 80);

    // ---- f2 fill slots (2 per thread at 480 threads) ----
    int f2base[2]; unsigned f2dst[2]; bool f2ok[2];
    #pragma unroll
    for (int k = 0; k < 2; ++k) {
        int j = tid + 480 * k;              // 0..959; copies are j<640
        int i = j / 5;
        int m = j - i * 5;
        int c   = i >> 4;
        int x2l = i & 15;
        int x2  = x2g0 + x2l;
        f2dst[k]  = sb + F2BASE + ((c * 16 + x2l) * 13 + 1 + m) * 16;
        f2ok[k]   = (j < 640) && ((unsigned)x2 < 80u);
        f2base[k] = c * 128000 + x2 * 20 + 4 * m;
    }

    // ---- zeroing (once per block) ----
    if (anyok) {
        float4 z4 = make_float4(0.f, 0.f, 0.f, 0.f);
        if (x2b == 0 || x2b == 5) {
            for (int i = tid; i < 7168; i += 480) ((float4*)smem)[i] = z4;
        } else {
            for (int i = tid; i < 512; i += 480) {
                int e   = i & 255;
                int cx  = e >> 1;
                int g   = (e & 1) * 6;
                int quad = F2BASEQ + (i >> 8) * (F2B / 16) + cx * 13 + g;
                ((float4*)smem)[quad] = z4;
            }
        }
    }
    __syncthreads();

    // ---- prologue: full f1 tile once + first valid di's f2 phase 0 ----
    if (anyok) {
        #pragma unroll
        for (int k = 0; k < 8; ++k) {
            int idx = tid + 480 * k;        // 0..3839 quads
            int c  = idx / 120;
            int r  = idx - c * 120;
            int xl = r / 5;
            int q  = r - xl * 5;
            int xg = x2g0 + xl - 4;
            if ((unsigned)xg < 80u)
                cp16(sb + idx * 16,
                     f1 + c * 128000 + y * 1600 + xg * 20 + 4 * q);
        }
        int fd = (y2_0 < 0) ? -y2_0 : 0;    // first valid dil
        int yf = y2_0 + fd;
        if (f2ok[0]) cp16(f2dst[0], f2 + f2base[0] + yf * 1600);
        if (f2ok[1]) cp16(f2dst[1], f2 + f2base[1] + yf * 1600);
    }
    cp_commit();

    const int aq0 = (x2c + 8 - djg * 3) * 10 + zp;  // f1 pair idx (jl subtracts 10)
    const int bq0 = x2c * 26 + 1 + zp;              // f2 pair idx within channel

    int g = 0;   // processed-phase counter (parity = buffer select)

    #pragma unroll 1
    for (int dil = 0; dil < 3; ++dil) {
        const int y2 = y2_0 + dil;
        const bool yok = ((unsigned)y2 < 80u);

        ull acc[15];
        #pragma unroll
        for (int i = 0; i < 15; ++i) acc[i] = 0ull;

        if (yok) {
            #pragma unroll 2
            for (int p = 0; p < 4; ++p) {
                const int cur = g & 1;
                cp_wait<0>();
                __syncthreads();
                // issue next fills into buf[(g+1)&1] (overlaps compute of phase p)
                {
                    const unsigned b2 = ((g + 1) & 1) * F2B;
                    if (p < 3) {
                        const int adv = y2 * 1600 + (p + 1) * CADV;
                        if (f2ok[0]) cp16(f2dst[0] + b2, f2 + f2base[0] + adv);
                        if (f2ok[1]) cp16(f2dst[1] + b2, f2 + f2base[1] + adv);
                    } else {
                        int nd = dil + 1;
                        int ny = y2 + 1;
                        if (nd < 3 && ny >= 80) { nd = 3; }   // past end
                        if (nd < 3 && ny < 0)   { nd++; ny++; }
                        if (nd < 3) {
                            const int adv = ny * 1600;
                            if (f2ok[0]) cp16(f2dst[0] + b2, f2 + f2base[0] + adv);
                            if (f2ok[1]) cp16(f2dst[1] + b2, f2 + f2base[1] + adv);
                        }
                    }
                    cp_commit();
                }
                // ---- compute phase p from buf[cur] ----
                const ull* f1p = (const ull*)smem + p * 1920;   // 8 channels
                const ull* f2p = (const ull*)(smem + (F2BASE + cur * F2B) / 4);
                BW B0, B1;
                ull A0, A1, A2;
                loadB(B0, f2p, 0, bq0);
                A0 = loadA(f1p, 0, aq0);
                A1 = loadA(f1p, 0, aq0 - 10);
                A2 = loadA(f1p, 0, aq0 - 20);
                loadB(B1, f2p, 1, bq0);
                #pragma unroll
                for (int cl = 0; cl < 8; ++cl) {
                    const BW& Bc = (cl & 1) ? B1 : B0;
                    ull O1 = shiftpair(Bc.E0, Bc.E1);
                    ull O3 = shiftpair(Bc.E1, Bc.E2);
                    fma5(acc +  0, A0, Bc, O1, O3);
                    if (cl < 7) A0 = loadA(f1p, cl + 1, aq0);
                    fma5(acc +  5, A1, Bc, O1, O3);
                    if (cl < 7) A1 = loadA(f1p, cl + 1, aq0 - 10);
                    fma5(acc + 10, A2, Bc, O1, O3);
                    if (cl < 7) A2 = loadA(f1p, cl + 1, aq0 - 20);
                    if (cl < 6) loadB((cl & 1) ? B1 : B0, f2p, cl + 2, bq0);
                }
                ++g;
            }
        }

        // ---- epilogue for this di (overlaps next di's in-flight fills) ----
        {
            const int di = dig * 3 + dil;
            const bool x2ok = ((unsigned)x2g < 80u);
            const bool spin = yok && x2ok;
            const float m2v = spin ? g_mask2[y2 * 80 + x2g] : 1.f;
            const float inv = 1.f / 32.f;
            #pragma unroll
            for (int jl = 0; jl < 3; ++jl) {
                const int dj = djg * 3 + jl;
                const int x  = x2g + 4 - dj;
                if ((unsigned)x < 80u) {
                    const float m1  = g_mask1[y * 80 + x];
                    const float mIn = m1 * m2v;
                    float* pc = out + (size_t)(di * 9 + dj) * 128000
                                    + y * 1600 + x * 20 + 2 * zp;
                    float* pm = pc + NTOT;
                    #pragma unroll
                    for (int dk = 0; dk < 5; ++dk) {
                        float2 cv;
                        unpack2(acc[jl * 5 + dk], cv.x, cv.y);
                        cv.x *= inv; cv.y *= inv;
                        *(float2*)pc = cv;
                        float2 mv;
                        {
                            int z2a = 2 * zp + dk - 2;
                            mv.x = ((unsigned)z2a       < 20u) ? mIn : m1;
                            mv.y = ((unsigned)(z2a + 1) < 20u) ? mIn : m1;
                        }
                        *(float2*)pm = mv;
                        pc += (size_t)81 * 128000;
                        pm += (size_t)81 * 128000;
                    }
                }
            }
        }
    }
}

extern "C" void kernel_launch(void* const* d_in, const int* in_sizes, int n_in,
                              void* d_out, int out_size)
{
    (void)in_sizes; (void)n_in; (void)out_size;
    const float* f1 = (const float*)d_in[0];
    const float* a1 = (const float*)d_in[1];
    const float* f2 = (const float*)d_in[2];
    const float* a2 = (const float*)d_in[3];
    float* out = (float*)d_out;

    cudaFuncSetAttribute(corr_kernel, cudaFuncAttributeMaxDynamicSharedMemorySize, 114688);

    mask_prep<<<25, 256>>>(a1, a2);
    corr_kernel<<<dim3(6, 80, 3), 480, 114688>>>(f1, f2, out);
}